// round 11
// baseline (speedup 1.0000x reference)
#include <cuda_runtime.h>
#include <cuda_fp16.h>
#include <cstdint>

#define D      16
#define LIB    969
#define KPAD   1024
#define TPB    128
#define TILE_M 128
#define NK16   64          // K16 steps over padded K

// Precomputed B fragments (masked coefficients, single fp16), laid out as
// mma.m16n8k16 col-major B fragments: [K16][lane] -> uint4 =
// {b0 nb0, b1 nb0, b0 nb1, b1 nb1}.
__device__ uint4 g_bfragH[NK16 * 32];

// ---------------- helpers ----------------
__device__ __forceinline__ uint32_t smem_u32(const void* p) {
    uint32_t a;
    asm("{ .reg .u64 t; cvta.to.shared.u64 t, %1; cvt.u32.u64 %0, t; }"
        : "=r"(a) : "l"(p));
    return a;
}
#define LDSM4(r0, r1, r2, r3, addr)                                         \
    asm volatile("ldmatrix.sync.aligned.m8n8.x4.shared.b16 {%0,%1,%2,%3}, [%4];" \
                 : "=r"(r0), "=r"(r1), "=r"(r2), "=r"(r3) : "r"(addr))
#define MMA(d, a0, a1, a2, a3, b0, b1)                                      \
    asm volatile("mma.sync.aligned.m16n8k16.row.col.f32.f16.f16.f32 "       \
                 "{%0,%1,%2,%3}, {%4,%5,%6,%7}, {%8,%9}, {%0,%1,%2,%3};"    \
                 : "+f"((d)[0]), "+f"((d)[1]), "+f"((d)[2]), "+f"((d)[3])   \
                 : "r"(a0), "r"(a1), "r"(a2), "r"(a3), "r"(b0), "r"(b1))

// ---------------- prep: mask -> single-fp16 B fragments ----------------
__global__ void prep_kernel(const float* __restrict__ coeff,
                            const float* __restrict__ fixedv,
                            const unsigned char* __restrict__ fmask)
{
    int id = blockIdx.x * blockDim.x + threadIdx.x;
    if (id >= NK16 * 32) return;           // (K16, lane)
    int K16  = id >> 5;
    int lane = id & 31;
    int g = lane >> 2, tig = lane & 3;
    int kks[4] = {2 * tig, 2 * tig + 1, 2 * tig + 8, 2 * tig + 9};
    unsigned short h[8];
#pragma unroll
    for (int nb = 0; nb < 2; nb++) {
        int n = nb * 8 + g;
#pragma unroll
        for (int e = 0; e < 4; e++) {
            int k = K16 * 16 + kks[e];
            float c = 0.f;
            if (k < LIB) { int s = k * D + n; c = fmask[s] ? fixedv[s] : coeff[s]; }
            h[nb * 4 + e] = __half_as_ushort(__float2half_rn(c));
        }
    }
    uint4 r;
    r.x = (uint32_t)h[0] | ((uint32_t)h[1] << 16);
    r.y = (uint32_t)h[2] | ((uint32_t)h[3] << 16);
    r.z = (uint32_t)h[4] | ((uint32_t)h[5] << 16);
    r.w = (uint32_t)h[6] | ((uint32_t)h[7] << 16);
    g_bfragH[K16 * 32 + lane] = r;
}

// ---------------- per-chunk MMA (R9 structure: sync at entry AND exit) --------
__device__ __forceinline__ void chunk_mma(int c, uint32_t sTh, uint32_t sTl,
                                          float (&acc)[2][2][4], int lane, int w)
{
    __syncwarp();
#pragma unroll
    for (int ks = 0; ks < 4; ks++) {
        uint4 bh = __ldg(&g_bfragH[(c * 4 + ks) * 32 + lane]);
#pragma unroll
        for (int ms = 0; ms < 2; ms++) {
            int rl   = w * 32 + ms * 16 + (lane & 15);
            int slot = 2 * ks + (lane >> 4);
            uint32_t off = (uint32_t)(rl * 128 + ((slot ^ (rl & 7)) << 4));
            uint32_t a0, a1, a2, a3, l0, l1, l2, l3;
            LDSM4(a0, a1, a2, a3, sTh + off);
            LDSM4(l0, l1, l2, l3, sTl + off);
            MMA(acc[ms][0], a0, a1, a2, a3, bh.x, bh.y);  // Th*C nb0
            MMA(acc[ms][1], a0, a1, a2, a3, bh.z, bh.w);  // Th*C nb1
            MMA(acc[ms][0], l0, l1, l2, l3, bh.x, bh.y);  // Tl*C nb0
            MMA(acc[ms][1], l0, l1, l2, l3, bh.z, bh.w);  // Tl*C nb1
        }
    }
    __syncwarp();
}

// ---------------- main kernel (R9 skeleton, fp16 theta hi/lo) ----------------
__global__ __launch_bounds__(TPB, 3) void sindy_kernel(
    const float* __restrict__ z,
    float* __restrict__ out,
    int B)
{
    __shared__ __align__(128) unsigned char sTheta[2 * 16384];  // hi | lo chunk tiles
    const uint32_t sTh = smem_u32(sTheta);
    const uint32_t sTl = sTh + 16384;

    const int tid  = threadIdx.x;
    const int lane = tid & 31;
    const int w    = tid >> 5;
    const uint32_t rowoff = (uint32_t)tid * 128;
    const int swz = tid & 7;

    const long row_g = (long)blockIdx.x * TILE_M + tid;
    const bool valid = row_g < B;

    float zv[D];
    {
        const float4* p = (const float4*)(z + row_g * D);
#pragma unroll
        for (int q = 0; q < 4; q++) {
            float4 t4 = valid ? p[q] : make_float4(0.f, 0.f, 0.f, 0.f);
            zv[4*q+0] = t4.x; zv[4*q+1] = t4.y; zv[4*q+2] = t4.z; zv[4*q+3] = t4.w;
        }
    }

    float acc[2][2][4];
#pragma unroll
    for (int a = 0; a < 2; a++)
#pragma unroll
        for (int b = 0; b < 2; b++)
#pragma unroll
            for (int e = 0; e < 4; e++) acc[a][b][e] = 0.f;

    float pend = 0.f;
    uint32_t hbuf[4], lbuf[4];
    int t = 0;   // compile-time folded (everything below fully unrolled)

#define EMIT(expr) do {                                                          \
        float m_ = (expr);                                                       \
        if ((t & 1) == 0) pend = m_;                                             \
        else {                                                                   \
            uint32_t hp_;                                                        \
            asm("cvt.rn.f16x2.f32 %0, %1, %2;" : "=r"(hp_) : "f"(m_), "f"(pend)); \
            float e0_, e1_;                                                      \
            asm("{ .reg .f16 h0_, h1_; mov.b32 {h0_, h1_}, %2;"                  \
                " cvt.f32.f16 %0, h0_; cvt.f32.f16 %1, h1_; }"                   \
                : "=f"(e0_), "=f"(e1_) : "r"(hp_));                              \
            float l0_ = pend - e0_;                                              \
            float l1_ = m_   - e1_;                                              \
            uint32_t lp_;                                                        \
            asm("cvt.rn.f16x2.f32 %0, %1, %2;" : "=r"(lp_) : "f"(l1_), "f"(l0_)); \
            hbuf[(t >> 1) & 3] = hp_;                                            \
            lbuf[(t >> 1) & 3] = lp_;                                            \
            if ((t & 7) == 7) {                                                  \
                int s_ = (t >> 3) & 7;                                           \
                uint32_t off_ = rowoff + (uint32_t)((s_ ^ swz) << 4);            \
                asm volatile("st.shared.v4.b32 [%0], {%1,%2,%3,%4};"             \
                    :: "r"(sTh + off_), "r"(hbuf[0]), "r"(hbuf[1]),              \
                       "r"(hbuf[2]), "r"(hbuf[3]) : "memory");                   \
                asm volatile("st.shared.v4.b32 [%0], {%1,%2,%3,%4};"             \
                    :: "r"(sTl + off_), "r"(lbuf[0]), "r"(lbuf[1]),              \
                       "r"(lbuf[2]), "r"(lbuf[3]) : "memory");                   \
            }                                                                    \
            if ((t & 63) == 63) chunk_mma(t >> 6, sTh, sTl, acc, lane, w);       \
        }                                                                        \
        t++;                                                                     \
    } while (0)

    EMIT(1.0f);                                      // constant term
#pragma unroll
    for (int i = 0; i < D; i++) EMIT(zv[i]);         // order 1
#pragma unroll
    for (int i = 0; i < D; i++)                      // order 2 (i<=j)
#pragma unroll
        for (int j = i; j < D; j++) EMIT(zv[i] * zv[j]);
#pragma unroll
    for (int i = 0; i < D; i++)                      // order 3 (i<=j<=k)
#pragma unroll
        for (int j = i; j < D; j++) {
            float pp = zv[i] * zv[j];
#pragma unroll
            for (int k = j; k < D; k++) EMIT(pp * zv[k]);
        }
#pragma unroll
    for (int pad = LIB; pad < KPAD; pad++) EMIT(0.0f);   // zero padding
#undef EMIT

    // Epilogue: D fragments -> out
    const int g = lane >> 2, tig = lane & 3;
    const long rbase = (long)blockIdx.x * TILE_M + w * 32;
#pragma unroll
    for (int ms = 0; ms < 2; ms++)
#pragma unroll
        for (int nb = 0; nb < 2; nb++) {
            long r0 = rbase + ms * 16 + g;
            long r1 = r0 + 8;
            int  cn = nb * 8 + 2 * tig;
            if (r0 < B)
                *(float2*)(out + r0 * D + cn) =
                    make_float2(acc[ms][nb][0], acc[ms][nb][1]);
            if (r1 < B)
                *(float2*)(out + r1 * D + cn) =
                    make_float2(acc[ms][nb][2], acc[ms][nb][3]);
        }
}

extern "C" void kernel_launch(void* const* d_in, const int* in_sizes, int n_in,
                              void* d_out, int out_size)
{
    const float*         zin    = (const float*)d_in[0];
    const float*         coeff  = (const float*)d_in[1];
    const float*         fixedv = (const float*)d_in[2];
    const unsigned char* fmask  = (const unsigned char*)d_in[3];
    float*               out    = (float*)d_out;

    const int B = in_sizes[0] / D;

    prep_kernel<<<(NK16 * 32 + 255) / 256, 256>>>(coeff, fixedv, fmask);

    const int grid = (B + TILE_M - 1) / TILE_M;
    sindy_kernel<<<grid, TPB>>>(zin, out, B);
}

// round 12
// speedup vs baseline: 1.1135x; 1.1135x over previous
#include <cuda_runtime.h>
#include <cuda_fp16.h>
#include <cstdint>

#define D      16
#define LIB    969
#define KPAD   1024
#define TPB    128
#define TILE_M 128
#define NK16   64          // K16 steps over padded K

// Precomputed B fragments: masked coefficients as fp16 hi + fp16 residual lo,
// mma.m16n8k16 col-major B layout: [K16][lane] -> uint4 =
// {b0 nb0, b1 nb0, b0 nb1, b1 nb1}; low 16 bits = even k.
__device__ uint4 g_bfragH[NK16 * 32];
__device__ uint4 g_bfragL[NK16 * 32];

// ---------------- helpers ----------------
__device__ __forceinline__ uint32_t smem_u32(const void* p) {
    uint32_t a;
    asm("{ .reg .u64 t; cvta.to.shared.u64 t, %1; cvt.u32.u64 %0, t; }"
        : "=r"(a) : "l"(p));
    return a;
}
#define LDSM4(r0, r1, r2, r3, addr)                                         \
    asm volatile("ldmatrix.sync.aligned.m8n8.x4.shared.b16 {%0,%1,%2,%3}, [%4];" \
                 : "=r"(r0), "=r"(r1), "=r"(r2), "=r"(r3) : "r"(addr))
#define MMA(d, a0, a1, a2, a3, b0, b1)                                      \
    asm volatile("mma.sync.aligned.m16n8k16.row.col.f32.f16.f16.f32 "       \
                 "{%0,%1,%2,%3}, {%4,%5,%6,%7}, {%8,%9}, {%0,%1,%2,%3};"    \
                 : "+f"((d)[0]), "+f"((d)[1]), "+f"((d)[2]), "+f"((d)[3])   \
                 : "r"(a0), "r"(a1), "r"(a2), "r"(a3), "r"(b0), "r"(b1))

__device__ __forceinline__ uint32_t h2_bits(__half2 h) {
    uint32_t u;
    __builtin_memcpy(&u, &h, 4);
    return u;
}

// ---------------- prep: mask + fp16 hi/lo split -> B fragments ----------------
__global__ void prep_kernel(const float* __restrict__ coeff,
                            const float* __restrict__ fixedv,
                            const unsigned char* __restrict__ fmask)
{
    int id = blockIdx.x * blockDim.x + threadIdx.x;
    if (id >= NK16 * 64) return;           // (K16, split, lane)
    int K16   = id >> 6;
    int split = (id >> 5) & 1;
    int lane  = id & 31;
    int g = lane >> 2, tig = lane & 3;
    int kks[4] = {2 * tig, 2 * tig + 1, 2 * tig + 8, 2 * tig + 9};
    unsigned short h[8];
#pragma unroll
    for (int nb = 0; nb < 2; nb++) {
        int n = nb * 8 + g;
#pragma unroll
        for (int e = 0; e < 4; e++) {
            int k = K16 * 16 + kks[e];
            float c = 0.f;
            if (k < LIB) { int s = k * D + n; c = fmask[s] ? fixedv[s] : coeff[s]; }
            __half hb = __float2half_rn(c);                    // hi
            __half lb = __float2half_rn(c - __half2float(hb)); // residual
            h[nb * 4 + e] = __half_as_ushort(split ? lb : hb);
        }
    }
    uint4 r;
    r.x = (uint32_t)h[0] | ((uint32_t)h[1] << 16);
    r.y = (uint32_t)h[2] | ((uint32_t)h[3] << 16);
    r.z = (uint32_t)h[4] | ((uint32_t)h[5] << 16);
    r.w = (uint32_t)h[6] | ((uint32_t)h[7] << 16);
    (split ? g_bfragL : g_bfragH)[K16 * 32 + lane] = r;
}

// ---------------- per-chunk MMA (R9 structure: sync at entry AND exit) --------
__device__ __forceinline__ void chunk_mma(int c, uint32_t sTh,
                                          float (&acc)[2][2][4], int lane, int w)
{
    __syncwarp();
#pragma unroll
    for (int ks = 0; ks < 4; ks++) {
        uint4 bh = __ldg(&g_bfragH[(c * 4 + ks) * 32 + lane]);
        uint4 bl = __ldg(&g_bfragL[(c * 4 + ks) * 32 + lane]);
#pragma unroll
        for (int ms = 0; ms < 2; ms++) {
            int rl   = w * 32 + ms * 16 + (lane & 15);
            int slot = 2 * ks + (lane >> 4);
            uint32_t off = (uint32_t)(rl * 128 + ((slot ^ (rl & 7)) << 4));
            uint32_t a0, a1, a2, a3;
            LDSM4(a0, a1, a2, a3, sTh + off);
            MMA(acc[ms][0], a0, a1, a2, a3, bh.x, bh.y);  // T*Ch nb0
            MMA(acc[ms][1], a0, a1, a2, a3, bh.z, bh.w);  // T*Ch nb1
            MMA(acc[ms][0], a0, a1, a2, a3, bl.x, bl.y);  // T*Cl nb0
            MMA(acc[ms][1], a0, a1, a2, a3, bl.z, bl.w);  // T*Cl nb1
        }
    }
    __syncwarp();
}

// ---------------- main kernel (R9 skeleton, single fp16 theta tile) -----------
__global__ __launch_bounds__(TPB, 3) void sindy_kernel(
    const float* __restrict__ z,
    float* __restrict__ out,
    int B)
{
    __shared__ __align__(128) unsigned char sTheta[16384];   // single fp16 tile
    const uint32_t sTh = smem_u32(sTheta);

    const int tid  = threadIdx.x;
    const int lane = tid & 31;
    const int w    = tid >> 5;
    const uint32_t rowoff = (uint32_t)tid * 128;
    const int swz = tid & 7;

    const long row_g = (long)blockIdx.x * TILE_M + tid;
    const bool valid = row_g < B;

    float zv[D];
    {
        const float4* p = (const float4*)(z + row_g * D);
#pragma unroll
        for (int q = 0; q < 4; q++) {
            float4 t4 = valid ? p[q] : make_float4(0.f, 0.f, 0.f, 0.f);
            zv[4*q+0] = t4.x; zv[4*q+1] = t4.y; zv[4*q+2] = t4.z; zv[4*q+3] = t4.w;
        }
    }

    float acc[2][2][4];
#pragma unroll
    for (int a = 0; a < 2; a++)
#pragma unroll
        for (int b = 0; b < 2; b++)
#pragma unroll
            for (int e = 0; e < 4; e++) acc[a][b][e] = 0.f;

    float pend = 0.f;
    uint32_t hbuf[4];
    int t = 0;   // compile-time folded (everything below fully unrolled)

#define EMIT(expr) do {                                                          \
        float m_ = (expr);                                                       \
        if ((t & 1) == 0) pend = m_;                                             \
        else {                                                                   \
            /* low half = even term (pend), high half = odd term (m_) */         \
            __half2 hp_ = __float22half2_rn(make_float2(pend, m_));              \
            hbuf[(t >> 1) & 3] = h2_bits(hp_);                                   \
            if ((t & 7) == 7) {                                                  \
                int s_ = (t >> 3) & 7;                                           \
                uint32_t off_ = rowoff + (uint32_t)((s_ ^ swz) << 4);            \
                asm volatile("st.shared.v4.b32 [%0], {%1,%2,%3,%4};"             \
                    :: "r"(sTh + off_), "r"(hbuf[0]), "r"(hbuf[1]),              \
                       "r"(hbuf[2]), "r"(hbuf[3]) : "memory");                   \
            }                                                                    \
            if ((t & 63) == 63) chunk_mma(t >> 6, sTh, acc, lane, w);            \
        }                                                                        \
        t++;                                                                     \
    } while (0)

    EMIT(1.0f);                                      // constant term
#pragma unroll
    for (int i = 0; i < D; i++) EMIT(zv[i]);         // order 1
#pragma unroll
    for (int i = 0; i < D; i++)                      // order 2 (i<=j)
#pragma unroll
        for (int j = i; j < D; j++) EMIT(zv[i] * zv[j]);
#pragma unroll
    for (int i = 0; i < D; i++)                      // order 3 (i<=j<=k)
#pragma unroll
        for (int j = i; j < D; j++) {
            float pp = zv[i] * zv[j];
#pragma unroll
            for (int k = j; k < D; k++) EMIT(pp * zv[k]);
        }
#pragma unroll
    for (int pad = LIB; pad < KPAD; pad++) EMIT(0.0f);   // zero padding
#undef EMIT

    // Epilogue: D fragments -> out
    const int g = lane >> 2, tig = lane & 3;
    const long rbase = (long)blockIdx.x * TILE_M + w * 32;
#pragma unroll
    for (int ms = 0; ms < 2; ms++)
#pragma unroll
        for (int nb = 0; nb < 2; nb++) {
            long r0 = rbase + ms * 16 + g;
            long r1 = r0 + 8;
            int  cn = nb * 8 + 2 * tig;
            if (r0 < B)
                *(float2*)(out + r0 * D + cn) =
                    make_float2(acc[ms][nb][0], acc[ms][nb][1]);
            if (r1 < B)
                *(float2*)(out + r1 * D + cn) =
                    make_float2(acc[ms][nb][2], acc[ms][nb][3]);
        }
}

extern "C" void kernel_launch(void* const* d_in, const int* in_sizes, int n_in,
                              void* d_out, int out_size)
{
    const float*         zin    = (const float*)d_in[0];
    const float*         coeff  = (const float*)d_in[1];
    const float*         fixedv = (const float*)d_in[2];
    const unsigned char* fmask  = (const unsigned char*)d_in[3];
    float*               out    = (float*)d_out;

    const int B = in_sizes[0] / D;

    prep_kernel<<<(NK16 * 64 + 255) / 256, 256>>>(coeff, fixedv, fmask);

    const int grid = (B + TILE_M - 1) / TILE_M;
    sindy_kernel<<<grid, TPB>>>(zin, out, B);
}

// round 13
// speedup vs baseline: 5.5750x; 5.0065x over previous
#include <cuda_runtime.h>
#include <cuda_bf16.h>
#include <cstdint>

#define D      16
#define LIB    969
#define KPAD   1024
#define TPB    128
#define TILE_M 128
#define NK16   64          // K16 steps over padded K

// Precomputed B fragments (masked coefficients, bf16 hi/lo split), laid out
// exactly as mma.m16n8k16 col-major B fragments: [K16][lane] -> uint4.
__device__ uint4 g_bfragH[NK16 * 32];
__device__ uint4 g_bfragL[NK16 * 32];

// ---------------- helpers ----------------
__device__ __forceinline__ uint32_t smem_u32(const void* p) {
    uint32_t a;
    asm("{ .reg .u64 t; cvta.to.shared.u64 t, %1; cvt.u32.u64 %0, t; }"
        : "=r"(a) : "l"(p));
    return a;
}
#define LDSM4(r0, r1, r2, r3, addr)                                         \
    asm volatile("ldmatrix.sync.aligned.m8n8.x4.shared.b16 {%0,%1,%2,%3}, [%4];" \
                 : "=r"(r0), "=r"(r1), "=r"(r2), "=r"(r3) : "r"(addr))
#define MMA(d, a0, a1, a2, a3, b0, b1)                                      \
    asm volatile("mma.sync.aligned.m16n8k16.row.col.f32.bf16.bf16.f32 "     \
                 "{%0,%1,%2,%3}, {%4,%5,%6,%7}, {%8,%9}, {%0,%1,%2,%3};"    \
                 : "+f"((d)[0]), "+f"((d)[1]), "+f"((d)[2]), "+f"((d)[3])   \
                 : "r"(a0), "r"(a1), "r"(a2), "r"(a3), "r"(b0), "r"(b1))

// ---------------- prep: mask + bf16 split -> B fragments ----------------
__global__ void prep_kernel(const float* __restrict__ coeff,
                            const float* __restrict__ fixedv,
                            const unsigned char* __restrict__ fmask)
{
    int id = blockIdx.x * blockDim.x + threadIdx.x;
    if (id >= NK16 * 64) return;           // (K16, split, lane)
    int K16   = id >> 6;
    int split = (id >> 5) & 1;
    int lane  = id & 31;
    int g = lane >> 2, tig = lane & 3;
    int kks[4] = {2 * tig, 2 * tig + 1, 2 * tig + 8, 2 * tig + 9};
    unsigned short h[8];
#pragma unroll
    for (int nb = 0; nb < 2; nb++) {
        int n = nb * 8 + g;
#pragma unroll
        for (int e = 0; e < 4; e++) {
            int k = K16 * 16 + kks[e];
            float c = 0.f;
            if (k < LIB) { int s = k * D + n; c = fmask[s] ? fixedv[s] : coeff[s]; }
            __nv_bfloat16 hb = __float2bfloat16(c);            // RN hi
            float hf = __bfloat162float(hb);
            __nv_bfloat16 lb = __float2bfloat16(c - hf);       // residual
            h[nb * 4 + e] = __bfloat16_as_ushort(split ? lb : hb);
        }
    }
    uint4 r;
    r.x = (uint32_t)h[0] | ((uint32_t)h[1] << 16);
    r.y = (uint32_t)h[2] | ((uint32_t)h[3] << 16);
    r.z = (uint32_t)h[4] | ((uint32_t)h[5] << 16);
    r.w = (uint32_t)h[6] | ((uint32_t)h[7] << 16);
    (split ? g_bfragL : g_bfragH)[K16 * 32 + lane] = r;
}

// ---------------- per-chunk MMA ----------------
// B-fragment LDGs hoisted to the top (latency overlaps the LDSM stream).
// No trailing syncwarp: in-order issue means the next chunk's STS cannot
// issue before this chunk's MMAs, which already waited on LDSM results.
__device__ __forceinline__ void chunk_mma(int c, uint32_t sTh, uint32_t sTl,
                                          float (&acc)[2][2][4], int lane, int w)
{
    __syncwarp();
    uint4 bh[4], bl[4];
#pragma unroll
    for (int ks = 0; ks < 4; ks++) {
        bh[ks] = __ldg(&g_bfragH[(c * 4 + ks) * 32 + lane]);
        bl[ks] = __ldg(&g_bfragL[(c * 4 + ks) * 32 + lane]);
    }
#pragma unroll
    for (int ks = 0; ks < 4; ks++) {
#pragma unroll
        for (int ms = 0; ms < 2; ms++) {
            int rl   = w * 32 + ms * 16 + (lane & 15);
            int slot = 2 * ks + (lane >> 4);
            uint32_t off = (uint32_t)(rl * 128 + ((slot ^ (rl & 7)) << 4));
            uint32_t a0, a1, a2, a3, l0, l1, l2, l3;
            LDSM4(a0, a1, a2, a3, sTh + off);
            LDSM4(l0, l1, l2, l3, sTl + off);
            MMA(acc[ms][0], a0, a1, a2, a3, bh[ks].x, bh[ks].y);  // Th*Ch nb0
            MMA(acc[ms][1], a0, a1, a2, a3, bh[ks].z, bh[ks].w);  // Th*Ch nb1
            MMA(acc[ms][0], l0, l1, l2, l3, bh[ks].x, bh[ks].y);  // Tl*Ch
            MMA(acc[ms][1], l0, l1, l2, l3, bh[ks].z, bh[ks].w);
            MMA(acc[ms][0], a0, a1, a2, a3, bl[ks].x, bl[ks].y);  // Th*Cl
            MMA(acc[ms][1], a0, a1, a2, a3, bl[ks].z, bl[ks].w);
        }
    }
}

// ---------------- main kernel (R9 skeleton) ----------------
__global__ __launch_bounds__(TPB, 3) void sindy_kernel(
    const float* __restrict__ z,
    float* __restrict__ out,
    int B)
{
    __shared__ __align__(128) unsigned char sTheta[2 * 16384];  // hi | lo chunk tiles
    const uint32_t sTh = smem_u32(sTheta);
    const uint32_t sTl = sTh + 16384;

    const int tid  = threadIdx.x;
    const int lane = tid & 31;
    const int w    = tid >> 5;
    const uint32_t rowoff = (uint32_t)tid * 128;
    const int swz = tid & 7;

    const long row_g = (long)blockIdx.x * TILE_M + tid;
    const bool valid = row_g < B;

    float zv[D];
    {
        const float4* p = (const float4*)(z + row_g * D);
#pragma unroll
        for (int q = 0; q < 4; q++) {
            float4 t4 = valid ? p[q] : make_float4(0.f, 0.f, 0.f, 0.f);
            zv[4*q+0] = t4.x; zv[4*q+1] = t4.y; zv[4*q+2] = t4.z; zv[4*q+3] = t4.w;
        }
    }

    float acc[2][2][4];
#pragma unroll
    for (int a = 0; a < 2; a++)
#pragma unroll
        for (int b = 0; b < 2; b++)
#pragma unroll
            for (int e = 0; e < 4; e++) acc[a][b][e] = 0.f;

    float pend = 0.f;
    uint32_t hbuf[4], lbuf[4];
    int t = 0;   // compile-time folded (everything below fully unrolled)

#define EMIT(expr) do {                                                          \
        float m_ = (expr);                                                       \
        if ((t & 1) == 0) pend = m_;                                             \
        else {                                                                   \
            uint32_t hp_;                                                        \
            asm("cvt.rn.bf16x2.f32 %0, %1, %2;" : "=r"(hp_) : "f"(m_), "f"(pend)); \
            float e0_ = __uint_as_float(hp_ << 16);                              \
            float e1_ = __uint_as_float(hp_ & 0xFFFF0000u);                      \
            float l0_ = pend - e0_;                                              \
            float l1_ = m_   - e1_;                                              \
            uint32_t lp_;                                                        \
            asm("cvt.rn.bf16x2.f32 %0, %1, %2;" : "=r"(lp_) : "f"(l1_), "f"(l0_)); \
            hbuf[(t >> 1) & 3] = hp_;                                            \
            lbuf[(t >> 1) & 3] = lp_;                                            \
            if ((t & 7) == 7) {                                                  \
                int s_ = (t >> 3) & 7;                                           \
                uint32_t off_ = rowoff + (uint32_t)((s_ ^ swz) << 4);            \
                asm volatile("st.shared.v4.b32 [%0], {%1,%2,%3,%4};"             \
                    :: "r"(sTh + off_), "r"(hbuf[0]), "r"(hbuf[1]),              \
                       "r"(hbuf[2]), "r"(hbuf[3]) : "memory");                   \
                asm volatile("st.shared.v4.b32 [%0], {%1,%2,%3,%4};"             \
                    :: "r"(sTl + off_), "r"(lbuf[0]), "r"(lbuf[1]),              \
                       "r"(lbuf[2]), "r"(lbuf[3]) : "memory");                   \
            }                                                                    \
            if ((t & 63) == 63) chunk_mma(t >> 6, sTh, sTl, acc, lane, w);       \
        }                                                                        \
        t++;                                                                     \
    } while (0)

    EMIT(1.0f);                                      // constant term
#pragma unroll
    for (int i = 0; i < D; i++) EMIT(zv[i]);         // order 1
#pragma unroll
    for (int i = 0; i < D; i++)                      // order 2 (i<=j)
#pragma unroll
        for (int j = i; j < D; j++) EMIT(zv[i] * zv[j]);
#pragma unroll
    for (int i = 0; i < D; i++)                      // order 3 (i<=j<=k)
#pragma unroll
        for (int j = i; j < D; j++) {
            float pp = zv[i] * zv[j];
#pragma unroll
            for (int k = j; k < D; k++) EMIT(pp * zv[k]);
        }
#pragma unroll
    for (int pad = LIB; pad < KPAD; pad++) EMIT(0.0f);   // zero padding
#undef EMIT

    // Epilogue: D fragments -> out
    const int g = lane >> 2, tig = lane & 3;
    const long rbase = (long)blockIdx.x * TILE_M + w * 32;
#pragma unroll
    for (int ms = 0; ms < 2; ms++)
#pragma unroll
        for (int nb = 0; nb < 2; nb++) {
            long r0 = rbase + ms * 16 + g;
            long r1 = r0 + 8;
            int  cn = nb * 8 + 2 * tig;
            if (r0 < B)
                *(float2*)(out + r0 * D + cn) =
                    make_float2(acc[ms][nb][0], acc[ms][nb][1]);
            if (r1 < B)
                *(float2*)(out + r1 * D + cn) =
                    make_float2(acc[ms][nb][2], acc[ms][nb][3]);
        }
}

extern "C" void kernel_launch(void* const* d_in, const int* in_sizes, int n_in,
                              void* d_out, int out_size)
{
    const float*         zin    = (const float*)d_in[0];
    const float*         coeff  = (const float*)d_in[1];
    const float*         fixedv = (const float*)d_in[2];
    const unsigned char* fmask  = (const unsigned char*)d_in[3];
    float*               out    = (float*)d_out;

    const int B = in_sizes[0] / D;

    prep_kernel<<<(NK16 * 64 + 255) / 256, 256>>>(coeff, fixedv, fmask);

    const int grid = (B + TILE_M - 1) / TILE_M;
    sindy_kernel<<<grid, TPB>>>(zin, out, B);
}

// round 15
// speedup vs baseline: 5.7223x; 1.0264x over previous
#include <cuda_runtime.h>
#include <cuda_bf16.h>
#include <cstdint>

#define D      16
#define LIB    969
#define KPAD   1024
#define TPB    128
#define TILE_M 128
#define NK16   64          // K16 steps over padded K

// Precomputed B fragments (masked coefficients, bf16 hi/lo split), laid out
// exactly as mma.m16n8k16 col-major B fragments: [K16][lane] -> uint4.
__device__ uint4 g_bfragH[NK16 * 32];
__device__ uint4 g_bfragL[NK16 * 32];

// ---------------- helpers ----------------
__device__ __forceinline__ uint32_t smem_u32(const void* p) {
    uint32_t a;
    asm("{ .reg .u64 t; cvta.to.shared.u64 t, %1; cvt.u32.u64 %0, t; }"
        : "=r"(a) : "l"(p));
    return a;
}
#define LDSM4(r0, r1, r2, r3, addr)                                         \
    asm volatile("ldmatrix.sync.aligned.m8n8.x4.shared.b16 {%0,%1,%2,%3}, [%4];" \
                 : "=r"(r0), "=r"(r1), "=r"(r2), "=r"(r3) : "r"(addr))
#define MMA(d, a0, a1, a2, a3, b0, b1)                                      \
    asm volatile("mma.sync.aligned.m16n8k16.row.col.f32.bf16.bf16.f32 "     \
                 "{%0,%1,%2,%3}, {%4,%5,%6,%7}, {%8,%9}, {%0,%1,%2,%3};"    \
                 : "+f"((d)[0]), "+f"((d)[1]), "+f"((d)[2]), "+f"((d)[3])   \
                 : "r"(a0), "r"(a1), "r"(a2), "r"(a3), "r"(b0), "r"(b1))

// Full-warp-safe swizzle: decorrelates banks across all 32 simultaneously
// stored rows (slot ^ row&7 ^ row>>3 -> 4 balanced lanes per bank-group),
// while within any 8-row ldmatrix fetch (row>>3 fixed) rows still map to
// distinct groups. Same formula on store and load sides -> consistent.
#define SWZ(row, slot) ((uint32_t)(((slot) ^ ((row) & 7) ^ (((row) >> 3) & 3)) << 4))

// ---------------- prep: mask + bf16 split -> B fragments ----------------
__global__ void prep_kernel(const float* __restrict__ coeff,
                            const float* __restrict__ fixedv,
                            const unsigned char* __restrict__ fmask)
{
    int id = blockIdx.x * blockDim.x + threadIdx.x;
    if (id >= NK16 * 64) return;           // (K16, split, lane)
    int K16   = id >> 6;
    int split = (id >> 5) & 1;
    int lane  = id & 31;
    int g = lane >> 2, tig = lane & 3;
    int kks[4] = {2 * tig, 2 * tig + 1, 2 * tig + 8, 2 * tig + 9};
    unsigned short h[8];
#pragma unroll
    for (int nb = 0; nb < 2; nb++) {
        int n = nb * 8 + g;
#pragma unroll
        for (int e = 0; e < 4; e++) {
            int k = K16 * 16 + kks[e];
            float c = 0.f;
            if (k < LIB) { int s = k * D + n; c = fmask[s] ? fixedv[s] : coeff[s]; }
            __nv_bfloat16 hb = __float2bfloat16(c);            // RN hi
            float hf = __bfloat162float(hb);
            __nv_bfloat16 lb = __float2bfloat16(c - hf);       // residual
            h[nb * 4 + e] = __bfloat16_as_ushort(split ? lb : hb);
        }
    }
    uint4 r;
    r.x = (uint32_t)h[0] | ((uint32_t)h[1] << 16);
    r.y = (uint32_t)h[2] | ((uint32_t)h[3] << 16);
    r.z = (uint32_t)h[4] | ((uint32_t)h[5] << 16);
    r.w = (uint32_t)h[6] | ((uint32_t)h[7] << 16);
    (split ? g_bfragL : g_bfragH)[K16 * 32 + lane] = r;
}

// ---------------- per-chunk MMA ----------------
// B-fragment LDGs hoisted; no trailing syncwarp (R13-validated). nks < 4
// skips trailing k-steps whose theta AND coefficients are entirely zero.
__device__ __forceinline__ void chunk_mma(int c, int nks, uint32_t sTh, uint32_t sTl,
                                          float (&acc)[2][2][4], int lane, int w)
{
    __syncwarp();
    uint4 bh[4], bl[4];
#pragma unroll
    for (int ks = 0; ks < 4; ks++) {
        if (ks >= nks) break;
        bh[ks] = __ldg(&g_bfragH[(c * 4 + ks) * 32 + lane]);
        bl[ks] = __ldg(&g_bfragL[(c * 4 + ks) * 32 + lane]);
    }
#pragma unroll
    for (int ks = 0; ks < 4; ks++) {
        if (ks >= nks) break;
#pragma unroll
        for (int ms = 0; ms < 2; ms++) {
            int rl   = w * 32 + ms * 16 + (lane & 15);
            int slot = 2 * ks + (lane >> 4);
            uint32_t off = (uint32_t)(rl * 128) + SWZ(rl, slot);
            uint32_t a0, a1, a2, a3, l0, l1, l2, l3;
            LDSM4(a0, a1, a2, a3, sTh + off);
            LDSM4(l0, l1, l2, l3, sTl + off);
            MMA(acc[ms][0], a0, a1, a2, a3, bh[ks].x, bh[ks].y);  // Th*Ch nb0
            MMA(acc[ms][1], a0, a1, a2, a3, bh[ks].z, bh[ks].w);  // Th*Ch nb1
            MMA(acc[ms][0], l0, l1, l2, l3, bh[ks].x, bh[ks].y);  // Tl*Ch
            MMA(acc[ms][1], l0, l1, l2, l3, bh[ks].z, bh[ks].w);
            MMA(acc[ms][0], a0, a1, a2, a3, bl[ks].x, bl[ks].y);  // Th*Cl
            MMA(acc[ms][1], a0, a1, a2, a3, bl[ks].z, bl[ks].w);
        }
    }
}

// ---------------- main kernel ----------------
__global__ __launch_bounds__(TPB, 3) void sindy_kernel(
    const float* __restrict__ z,
    float* __restrict__ out,
    int B)
{
    __shared__ __align__(128) unsigned char sTheta[2 * 16384];  // hi | lo chunk tiles
    const uint32_t sTh = smem_u32(sTheta);
    const uint32_t sTl = sTh + 16384;

    const int tid  = threadIdx.x;
    const int lane = tid & 31;
    const int w    = tid >> 5;
    const uint32_t rowoff = (uint32_t)tid * 128;

    const long row_g = (long)blockIdx.x * TILE_M + tid;
    const bool valid = row_g < B;

    float zv[D];
    {
        const float4* p = (const float4*)(z + row_g * D);
#pragma unroll
        for (int q = 0; q < 4; q++) {
            float4 t4 = valid ? p[q] : make_float4(0.f, 0.f, 0.f, 0.f);
            zv[4*q+0] = t4.x; zv[4*q+1] = t4.y; zv[4*q+2] = t4.z; zv[4*q+3] = t4.w;
        }
    }

    float acc[2][2][4];
#pragma unroll
    for (int a = 0; a < 2; a++)
#pragma unroll
        for (int b = 0; b < 2; b++)
#pragma unroll
            for (int e = 0; e < 4; e++) acc[a][b][e] = 0.f;

    float pend = 0.f;
    uint32_t hbuf[4], lbuf[4];
    int t = 0;   // compile-time folded (everything below fully unrolled)

#define EMIT(expr) do {                                                          \
        float m_ = (expr);                                                       \
        if ((t & 1) == 0) pend = m_;                                             \
        else {                                                                   \
            uint32_t hp_;                                                        \
            asm("cvt.rn.bf16x2.f32 %0, %1, %2;" : "=r"(hp_) : "f"(m_), "f"(pend)); \
            float e0_ = __uint_as_float(hp_ << 16);                              \
            float e1_ = __uint_as_float(hp_ & 0xFFFF0000u);                      \
            float l0_ = pend - e0_;                                              \
            float l1_ = m_   - e1_;                                              \
            uint32_t lp_;                                                        \
            asm("cvt.rn.bf16x2.f32 %0, %1, %2;" : "=r"(lp_) : "f"(l1_), "f"(l0_)); \
            hbuf[(t >> 1) & 3] = hp_;                                            \
            lbuf[(t >> 1) & 3] = lp_;                                            \
            if ((t & 7) == 7) {                                                  \
                int s_ = (t >> 3) & 7;                                           \
                uint32_t off_ = rowoff + SWZ(tid, s_);                           \
                asm volatile("st.shared.v4.b32 [%0], {%1,%2,%3,%4};"             \
                    :: "r"(sTh + off_), "r"(hbuf[0]), "r"(hbuf[1]),              \
                       "r"(hbuf[2]), "r"(hbuf[3]) : "memory");                   \
                asm volatile("st.shared.v4.b32 [%0], {%1,%2,%3,%4};"             \
                    :: "r"(sTl + off_), "r"(lbuf[0]), "r"(lbuf[1]),              \
                       "r"(lbuf[2]), "r"(lbuf[3]) : "memory");                   \
            }                                                                    \
            if ((t & 63) == 63 && t < 960)                                       \
                chunk_mma(t >> 6, 4, sTh, sTl, acc, lane, w);                    \
        }                                                                        \
        t++;                                                                     \
    } while (0)

    EMIT(1.0f);                                      // constant term
#pragma unroll
    for (int i = 0; i < D; i++) EMIT(zv[i]);         // order 1
#pragma unroll
    for (int i = 0; i < D; i++)                      // order 2 (i<=j)
#pragma unroll
        for (int j = i; j < D; j++) EMIT(zv[i] * zv[j]);
#pragma unroll
    for (int i = 0; i < D; i++)                      // order 3 (i<=j<=k)
#pragma unroll
        for (int j = i; j < D; j++) {
            float pp = zv[i] * zv[j];
#pragma unroll
            for (int k = j; k < D; k++) EMIT(pp * zv[k]);
        }
    // Pad to 976 so the final chunk's single k-step (K16=60, k 960..975) has
    // both its theta slots stored. Terms/coefficients for k>=976 are all zero
    // on both sides and are skipped entirely.
#pragma unroll
    for (int pad = LIB; pad < 976; pad++) EMIT(0.0f);
#undef EMIT
    chunk_mma(15, 1, sTh, sTl, acc, lane, w);        // final chunk, 1 k-step

    // Epilogue: D fragments -> out
    const int g = lane >> 2, tig = lane & 3;
    const long rbase = (long)blockIdx.x * TILE_M + w * 32;
#pragma unroll
    for (int ms = 0; ms < 2; ms++)
#pragma unroll
        for (int nb = 0; nb < 2; nb++) {
            long r0 = rbase + ms * 16 + g;
            long r1 = r0 + 8;
            int  cn = nb * 8 + 2 * tig;
            if (r0 < B)
                *(float2*)(out + r0 * D + cn) =
                    make_float2(acc[ms][nb][0], acc[ms][nb][1]);
            if (r1 < B)
                *(float2*)(out + r1 * D + cn) =
                    make_float2(acc[ms][nb][2], acc[ms][nb][3]);
        }
}

extern "C" void kernel_launch(void* const* d_in, const int* in_sizes, int n_in,
                              void* d_out, int out_size)
{
    const float*         zin    = (const float*)d_in[0];
    const float*         coeff  = (const float*)d_in[1];
    const float*         fixedv = (const float*)d_in[2];
    const unsigned char* fmask  = (const unsigned char*)d_in[3];
    float*               out    = (float*)d_out;

    const int B = in_sizes[0] / D;

    prep_kernel<<<(NK16 * 64 + 255) / 256, 256>>>(coeff, fixedv, fmask);

    const int grid = (B + TILE_M - 1) / TILE_M;
    sindy_kernel<<<grid, TPB>>>(zin, out, B);
}